// round 14
// baseline (speedup 1.0000x reference)
#include <cuda_runtime.h>

#define D_   24
#define F_   48           // NK*D
#define H_   64
#define DEG_ 32
#define NW   8            // warps per block
#define NPW  8            // nodes per warp (sequential rounds)
#define NPB  (NW * NPW)   // 64 nodes per block
#define TPB  (NW * 32)    // 256 threads
#define FS   12           // featW g-stride (float4-aligned reads)
#define WRS  52           // Wrow h-stride (52/4=13 odd -> conflict-free LDS.128)

typedef unsigned long long u64;

__device__ __forceinline__ u64 pack2(float lo, float hi) {
    u64 r; asm("mov.b64 %0, {%1, %2};" : "=l"(r) : "f"(lo), "f"(hi)); return r;
}
__device__ __forceinline__ void unpack2(float& lo, float& hi, u64 v) {
    asm("mov.b64 {%0, %1}, %2;" : "=f"(lo), "=f"(hi) : "l"(v));
}
__device__ __forceinline__ u64 ffma2(u64 a, u64 b, u64 c) {
    u64 d; asm("fma.rn.f32x2 %0, %1, %2, %3;" : "=l"(d) : "l"(a), "l"(b), "l"(c)); return d;
}

__global__ __launch_bounds__(TPB, 5) void gnn_fused_kernel(
    const float* __restrict__ x,        // [N, 24]
    const int* __restrict__ edge_idx,   // [2, E] int32; src = first E
    const float* __restrict__ kvals,    // [2, E]
    const float* __restrict__ W,        // [64, 48] row-major
    float* __restrict__ out,            // [N, 64]
    int N, int E)
{
    __shared__ __align__(16) float Wrow[H_ * WRS];     // 13 KB, Wrow[h*52+j]=W[h][j]
    __shared__ __align__(16) float featW[NW][F_ * FS]; // 18 KB
    __shared__ __align__(16) int   soff[NW][DEG_];     // 1 KB (src*96 byte offsets)
    __shared__ __align__(16) float sk0[NW][DEG_];      // 1 KB (k0 - 1/32)
    __shared__ __align__(16) float sk1[NW][DEG_];      // 1 KB (k1 - 1/32)

    const int tid  = threadIdx.x;
    const int w    = tid >> 5;
    const int lane = tid & 31;

    // Stage W row-major, padded stride (coalesced LDG, conflict-free STS)
    for (int idx = tid; idx < H_ * F_; idx += TPB) {
        const int h = idx / F_, j = idx - h * F_;
        Wrow[h * WRS + j] = W[idx];
    }

    const int  base  = blockIdx.x * NPB + w * NPW;
    const bool pred  = lane < D_;
    const char* xlane = (const char*)(x + lane);

    // ---- Gather: 8 sequential nodes per warp ----
    #pragma unroll 1
    for (int r = 0; r < NPW; ++r) {
        const int  node  = base + r;
        const bool valid = node < N;

        // Stage this round's edge metadata (k' = k - 1/32 folds neighbor mean)
        if (valid) {
            const int e = node * DEG_ + lane;
            soff[w][lane] = __ldg(edge_idx + e) * 96;
            sk0[w][lane]  = __ldg(kvals + e)     - 0.03125f;
            sk1[w][lane]  = __ldg(kvals + e + E) - 0.03125f;
        } else {
            soff[w][lane] = 0;
            sk0[w][lane]  = 0.f;
            sk1[w][lane]  = 0.f;
        }
        __syncwarp();

        const bool act = pred && valid;
        const float xi = act ? __ldg(x + node * D_ + lane) : 0.f;
        u64 acc0p = 0, acc1p = 0;   // (even-edge sum, odd-edge sum) packed

        #pragma unroll
        for (int c = 0; c < 4; ++c) {
            const int4 oa = *(const int4*)&soff[w][c * 8];
            const int4 ob = *(const int4*)&soff[w][c * 8 + 4];
            float xv[8];
            xv[0] = act ? __ldg((const float*)(xlane + oa.x)) : 0.f;
            xv[1] = act ? __ldg((const float*)(xlane + oa.y)) : 0.f;
            xv[2] = act ? __ldg((const float*)(xlane + oa.z)) : 0.f;
            xv[3] = act ? __ldg((const float*)(xlane + oa.w)) : 0.f;
            xv[4] = act ? __ldg((const float*)(xlane + ob.x)) : 0.f;
            xv[5] = act ? __ldg((const float*)(xlane + ob.y)) : 0.f;
            xv[6] = act ? __ldg((const float*)(xlane + ob.z)) : 0.f;
            xv[7] = act ? __ldg((const float*)(xlane + ob.w)) : 0.f;

            // k' pairs come packed straight from smem (broadcast LDS.128)
            const longlong2 k0q = *(const longlong2*)&sk0[w][c * 8];      // e(0,1),(2,3)
            const longlong2 k0r = *(const longlong2*)&sk0[w][c * 8 + 4];  // e(4,5),(6,7)
            const longlong2 k1q = *(const longlong2*)&sk1[w][c * 8];
            const longlong2 k1r = *(const longlong2*)&sk1[w][c * 8 + 4];

            const u64 xp0 = pack2(xv[0], xv[1]);
            const u64 xp1 = pack2(xv[2], xv[3]);
            const u64 xp2 = pack2(xv[4], xv[5]);
            const u64 xp3 = pack2(xv[6], xv[7]);

            acc0p = ffma2((u64)k0q.x, xp0, acc0p);
            acc0p = ffma2((u64)k0q.y, xp1, acc0p);
            acc0p = ffma2((u64)k0r.x, xp2, acc0p);
            acc0p = ffma2((u64)k0r.y, xp3, acc0p);
            acc1p = ffma2((u64)k1q.x, xp0, acc1p);
            acc1p = ffma2((u64)k1q.y, xp1, acc1p);
            acc1p = ffma2((u64)k1r.x, xp2, acc1p);
            acc1p = ffma2((u64)k1r.y, xp3, acc1p);
        }

        if (pred) {
            float a0l, a0h, a1l, a1h;
            unpack2(a0l, a0h, acc0p);
            unpack2(a1l, a1h, acc1p);
            featW[w][lane * FS + r]        = a0l + a0h + xi;   // feature j=lane
            featW[w][(lane + D_) * FS + r] = a1l + a1h + xi;   // feature j=lane+24
        }
        __syncwarp();   // all reads of soff/sk done before next round restages
    }

    __syncthreads();    // Wrow visible to all warps

    // ---- Epilogue: one W pass serves 8 nodes; W via LDS.128, node-pairs f32x2 ----
    u64 yA[4], yB[4];   // yA[p] = (y_ch(lane) node 2p, node 2p+1); yB = ch lane+32
    #pragma unroll
    for (int p = 0; p < 4; ++p) { yA[p] = 0; yB[p] = 0; }

    #pragma unroll
    for (int j = 0; j < F_; j += 4) {
        const float4 wv0 = *(const float4*)&Wrow[lane * WRS + j];        // ch lane
        const float4 wv1 = *(const float4*)&Wrow[(lane + 32) * WRS + j]; // ch lane+32
        #pragma unroll
        for (int q = 0; q < 4; ++q) {
            const float w0 = (q == 0) ? wv0.x : (q == 1) ? wv0.y : (q == 2) ? wv0.z : wv0.w;
            const float w1 = (q == 0) ? wv1.x : (q == 1) ? wv1.y : (q == 2) ? wv1.z : wv1.w;
            const u64 w0p = pack2(w0, w0);
            const u64 w1p = pack2(w1, w1);
            const longlong2 fa = *(const longlong2*)&featW[w][(j + q) * FS];      // (f0,f1)(f2,f3)
            const longlong2 fb = *(const longlong2*)&featW[w][(j + q) * FS + 4];  // (f4,f5)(f6,f7)
            yA[0] = ffma2(w0p, (u64)fa.x, yA[0]);
            yA[1] = ffma2(w0p, (u64)fa.y, yA[1]);
            yA[2] = ffma2(w0p, (u64)fb.x, yA[2]);
            yA[3] = ffma2(w0p, (u64)fb.y, yA[3]);
            yB[0] = ffma2(w1p, (u64)fa.x, yB[0]);
            yB[1] = ffma2(w1p, (u64)fa.y, yB[1]);
            yB[2] = ffma2(w1p, (u64)fb.x, yB[2]);
            yB[3] = ffma2(w1p, (u64)fb.y, yB[3]);
        }
    }

    #pragma unroll
    for (int p = 0; p < 4; ++p) {
        const int n0 = base + 2 * p, n1 = n0 + 1;
        float aLo, aHi, bLo, bHi;
        unpack2(aLo, aHi, yA[p]);
        unpack2(bLo, bHi, yB[p]);
        if (n0 < N) {
            out[n0 * H_ + lane]      = aLo;
            out[n0 * H_ + lane + 32] = bLo;
        }
        if (n1 < N) {
            out[n1 * H_ + lane]      = aHi;
            out[n1 * H_ + lane + 32] = bHi;
        }
    }
}

extern "C" void kernel_launch(void* const* d_in, const int* in_sizes, int n_in,
                              void* d_out, int out_size) {
    const float* x    = (const float*)d_in[0];      // [N, 24]
    const int*   eidx = (const int*)d_in[1];        // [2, E] int32
    const float* kv   = (const float*)d_in[2];      // [2, E]
    const float* W    = (const float*)d_in[3];      // [64, 48]
    float*       out  = (float*)d_out;

    const int N = in_sizes[0] / D_;
    const int E = in_sizes[2] / 2;

    const int blocks = (N + NPB - 1) / NPB;
    gnn_fused_kernel<<<blocks, TPB>>>(x, eidx, kv, W, out, N, E);
}

// round 15
// speedup vs baseline: 1.0871x; 1.0871x over previous
#include <cuda_runtime.h>

#define D_   24
#define F_   48           // NK*D
#define H_   64
#define DEG_ 32
#define NW   8            // warps per block
#define NPW  8            // nodes per warp (sequential rounds)
#define NPB  (NW * NPW)   // 64 nodes per block
#define TPB  (NW * 32)    // 256 threads
#define FS   12           // featW g-stride (float4-aligned reads)
#define WRS  52           // Wrow h-stride (52/4=13 odd -> conflict-free LDS.128)

typedef unsigned long long u64;

__device__ __forceinline__ u64 pack2(float lo, float hi) {
    u64 r; asm("mov.b64 %0, {%1, %2};" : "=l"(r) : "f"(lo), "f"(hi)); return r;
}
__device__ __forceinline__ void unpack2(float& lo, float& hi, u64 v) {
    asm("mov.b64 {%0, %1}, %2;" : "=f"(lo), "=f"(hi) : "l"(v));
}
__device__ __forceinline__ u64 ffma2(u64 a, u64 b, u64 c) {
    u64 d; asm("fma.rn.f32x2 %0, %1, %2, %3;" : "=l"(d) : "l"(a), "l"(b), "l"(c)); return d;
}

__global__ __launch_bounds__(TPB, 4) void gnn_fused_kernel(
    const float* __restrict__ x,        // [N, 24]
    const int* __restrict__ edge_idx,   // [2, E] int32; src = first E
    const float* __restrict__ kvals,    // [2, E]
    const float* __restrict__ W,        // [64, 48] row-major
    float* __restrict__ out,            // [N, 64]
    int N, int E)
{
    __shared__ __align__(16) float Wrow[H_ * WRS];     // 13 KB, Wrow[h*52+j]=W[h][j]
    __shared__ __align__(16) float featW[NW][F_ * FS]; // 18 KB
    __shared__ __align__(16) int   soff[NW][DEG_];     // 1 KB (src*96 byte offsets)
    __shared__ __align__(16) float sk0[NW][DEG_];      // 1 KB (k0 - 1/32)
    __shared__ __align__(16) float sk1[NW][DEG_];      // 1 KB (k1 - 1/32)

    const int tid  = threadIdx.x;
    const int w    = tid >> 5;
    const int lane = tid & 31;

    // Stage W row-major, padded stride (coalesced LDG, conflict-free STS)
    for (int idx = tid; idx < H_ * F_; idx += TPB) {
        const int h = idx / F_, j = idx - h * F_;
        Wrow[h * WRS + j] = W[idx];
    }
    // Sync HERE (all warps arrive together) instead of between gather and
    // epilogue — each warp then runs gather -> epilogue with no straggler wait.
    __syncthreads();

    const int  base  = blockIdx.x * NPB + w * NPW;
    const bool pred  = lane < D_;
    const char* xlane = (const char*)(x + lane);

    // ---- Prefetch round 0 staging (k' = k - 1/32 folds the neighbor mean) ----
    int off_n = 0; float k0_n = 0.f, k1_n = 0.f;
    if (base < N) {
        const int e0 = base * DEG_ + lane;
        off_n = edge_idx[e0] * 96;
        k0_n  = kvals[e0]     - 0.03125f;
        k1_n  = kvals[e0 + E] - 0.03125f;
    }

    // ---- Gather: 8 sequential nodes per warp, staging pipelined ----
    #pragma unroll 1
    for (int r = 0; r < NPW; ++r) {
        const int  node  = base + r;
        const bool valid = node < N;

        soff[w][lane] = off_n;
        sk0[w][lane]  = k0_n;
        sk1[w][lane]  = k1_n;
        __syncwarp();

        if (r + 1 < NPW) {          // prefetch next round (overlaps gathers)
            const int n2 = node + 1;
            off_n = 0; k0_n = 0.f; k1_n = 0.f;
            if (n2 < N) {
                const int e2 = n2 * DEG_ + lane;
                off_n = edge_idx[e2] * 96;
                k0_n  = kvals[e2]     - 0.03125f;
                k1_n  = kvals[e2 + E] - 0.03125f;
            }
        }

        const bool act = pred && valid;
        const float xi = act ? __ldg(x + node * D_ + lane) : 0.f;
        u64 acc0p = 0, acc1p = 0;   // (even-edge sum, odd-edge sum) packed

        #pragma unroll
        for (int c = 0; c < 4; ++c) {
            const int4 oa = *(const int4*)&soff[w][c * 8];
            const int4 ob = *(const int4*)&soff[w][c * 8 + 4];
            float xv[8];
            xv[0] = act ? __ldg((const float*)(xlane + oa.x)) : 0.f;
            xv[1] = act ? __ldg((const float*)(xlane + oa.y)) : 0.f;
            xv[2] = act ? __ldg((const float*)(xlane + oa.z)) : 0.f;
            xv[3] = act ? __ldg((const float*)(xlane + oa.w)) : 0.f;
            xv[4] = act ? __ldg((const float*)(xlane + ob.x)) : 0.f;
            xv[5] = act ? __ldg((const float*)(xlane + ob.y)) : 0.f;
            xv[6] = act ? __ldg((const float*)(xlane + ob.z)) : 0.f;
            xv[7] = act ? __ldg((const float*)(xlane + ob.w)) : 0.f;

            // k' pairs come packed straight from smem (broadcast LDS.128)
            const longlong2 k0q = *(const longlong2*)&sk0[w][c * 8];      // e(0,1),(2,3)
            const longlong2 k0r = *(const longlong2*)&sk0[w][c * 8 + 4];  // e(4,5),(6,7)
            const longlong2 k1q = *(const longlong2*)&sk1[w][c * 8];
            const longlong2 k1r = *(const longlong2*)&sk1[w][c * 8 + 4];

            const u64 xp0 = pack2(xv[0], xv[1]);
            const u64 xp1 = pack2(xv[2], xv[3]);
            const u64 xp2 = pack2(xv[4], xv[5]);
            const u64 xp3 = pack2(xv[6], xv[7]);

            acc0p = ffma2((u64)k0q.x, xp0, acc0p);
            acc0p = ffma2((u64)k0q.y, xp1, acc0p);
            acc0p = ffma2((u64)k0r.x, xp2, acc0p);
            acc0p = ffma2((u64)k0r.y, xp3, acc0p);
            acc1p = ffma2((u64)k1q.x, xp0, acc1p);
            acc1p = ffma2((u64)k1q.y, xp1, acc1p);
            acc1p = ffma2((u64)k1r.x, xp2, acc1p);
            acc1p = ffma2((u64)k1r.y, xp3, acc1p);
        }

        if (pred) {
            float a0l, a0h, a1l, a1h;
            unpack2(a0l, a0h, acc0p);
            unpack2(a1l, a1h, acc1p);
            featW[w][lane * FS + r]        = a0l + a0h + xi;   // feature j=lane
            featW[w][(lane + D_) * FS + r] = a1l + a1h + xi;   // feature j=lane+24
        }
        __syncwarp();
    }
    // NOTE: no __syncthreads here — featW is warp-private, Wrow already synced.

    // ---- Epilogue: one W pass serves 8 nodes; W via LDS.128, node-pairs f32x2 ----
    u64 yA[4], yB[4];   // yA[p] = (y_ch(lane) node 2p, node 2p+1); yB = ch lane+32
    #pragma unroll
    for (int p = 0; p < 4; ++p) { yA[p] = 0; yB[p] = 0; }

    #pragma unroll
    for (int j = 0; j < F_; j += 4) {
        const float4 wv0 = *(const float4*)&Wrow[lane * WRS + j];        // ch lane
        const float4 wv1 = *(const float4*)&Wrow[(lane + 32) * WRS + j]; // ch lane+32
        #pragma unroll
        for (int q = 0; q < 4; ++q) {
            const float w0 = (q == 0) ? wv0.x : (q == 1) ? wv0.y : (q == 2) ? wv0.z : wv0.w;
            const float w1 = (q == 0) ? wv1.x : (q == 1) ? wv1.y : (q == 2) ? wv1.z : wv1.w;
            const u64 w0p = pack2(w0, w0);
            const u64 w1p = pack2(w1, w1);
            const longlong2 fa = *(const longlong2*)&featW[w][(j + q) * FS];      // (f0,f1)(f2,f3)
            const longlong2 fb = *(const longlong2*)&featW[w][(j + q) * FS + 4];  // (f4,f5)(f6,f7)
            yA[0] = ffma2(w0p, (u64)fa.x, yA[0]);
            yA[1] = ffma2(w0p, (u64)fa.y, yA[1]);
            yA[2] = ffma2(w0p, (u64)fb.x, yA[2]);
            yA[3] = ffma2(w0p, (u64)fb.y, yA[3]);
            yB[0] = ffma2(w1p, (u64)fa.x, yB[0]);
            yB[1] = ffma2(w1p, (u64)fa.y, yB[1]);
            yB[2] = ffma2(w1p, (u64)fb.x, yB[2]);
            yB[3] = ffma2(w1p, (u64)fb.y, yB[3]);
        }
    }

    #pragma unroll
    for (int p = 0; p < 4; ++p) {
        const int n0 = base + 2 * p, n1 = n0 + 1;
        float aLo, aHi, bLo, bHi;
        unpack2(aLo, aHi, yA[p]);
        unpack2(bLo, bHi, yB[p]);
        if (n0 < N) {
            out[n0 * H_ + lane]      = aLo;
            out[n0 * H_ + lane + 32] = bLo;
        }
        if (n1 < N) {
            out[n1 * H_ + lane]      = aHi;
            out[n1 * H_ + lane + 32] = bHi;
        }
    }
}

extern "C" void kernel_launch(void* const* d_in, const int* in_sizes, int n_in,
                              void* d_out, int out_size) {
    const float* x    = (const float*)d_in[0];      // [N, 24]
    const int*   eidx = (const int*)d_in[1];        // [2, E] int32
    const float* kv   = (const float*)d_in[2];      // [2, E]
    const float* W    = (const float*)d_in[3];      // [64, 48]
    float*       out  = (float*)d_out;

    const int N = in_sizes[0] / D_;
    const int E = in_sizes[2] / 2;

    const int blocks = (N + NPB - 1) / NPB;
    gnn_fused_kernel<<<blocks, TPB>>>(x, eidx, kv, W, out, N, E);
}